// round 3
// baseline (speedup 1.0000x reference)
#include <cuda_runtime.h>

// out[b,o,d,h,w] = bias[o] + sum_{i=d-2..d+2 in [0,10)} sum_{kh,kw}
//                    x[b,i,h+kh-2,w+kw-2] * W[o,i,i-d+2,kh,kw]
//
// Inputs: x[32,10,128,128] f32, W[10,10,5,5,5] f32, b[10] f32
// Output: [32,10,10,128,128] f32
//
// R3: per-d CTA decomposition. Each CTA handles one (batch, 32x32 tile, d):
// smem drops to ~32KB (<=5 input channels + 1250-float weight slice),
// 3 CTAs/SM instead of 2 -> better latency hiding for the FFMA2 stream.

#define NB 32
#define NC 10
#define HW 128

typedef unsigned long long u64;

#define FMA2(d_, a_, b_, c_) \
    asm("fma.rn.f32x2 %0, %1, %2, %3;" : "=l"(d_) : "l"(a_), "l"(b_), "l"(c_))
#define PACK2(out_, lo_, hi_) \
    asm("mov.b64 %0, {%1, %2};" : "=l"(out_) : "f"(lo_), "f"(hi_))
#define UNPACK2(lo_, hi_, in_) \
    asm("mov.b64 {%0, %1}, %2;" : "=f"(lo_), "=f"(hi_) : "l"(in_))

// Repacked weights: [d][ip][kh][kw][o], zero where i=d+ip-2 out of range.
__device__ float g_Wr[10 * 5 * 5 * 5 * 10];

__global__ void repack_kernel(const float* __restrict__ W) {
    int idx = blockIdx.x * blockDim.x + threadIdx.x;
    if (idx >= 12500) return;
    int o    = idx % 10;
    int rest = idx / 10;
    int kw = rest % 5; rest /= 5;
    int kh = rest % 5; rest /= 5;
    int ip = rest % 5;
    int d  = rest / 5;
    int i = d + ip - 2;
    float v = 0.0f;
    if (i >= 0 && i < 10)
        v = W[o * 1250 + i * 125 + ip * 25 + kh * 5 + kw];
    g_Wr[idx] = v;
}

// SMEM: xs <=5ch x 36 x pitch37 | ws 1250 | bs 10
#define XS_FLOATS (5 * 36 * 37)      // 6660
#define WS_FLOATS 1250
#define SMEM_FLOATS (XS_FLOATS + WS_FLOATS + 10)   // 7920 floats = 31680 B

__global__ __launch_bounds__(256, 3) void conv_main(
    const float* __restrict__ x,
    const float* __restrict__ bias,
    float* __restrict__ out)
{
    extern __shared__ float smem[];
    float* xs = smem;
    float* ws = smem + XS_FLOATS;      // byte off 26640, 8B aligned
    float* bs = ws + WS_FLOATS;        // byte off 31640, 8B aligned

    // d fastest so the 10 CTAs sharing one x tile are adjacent in launch order
    const int d    = blockIdx.x % 10;
    const int rest = blockIdx.x / 10;
    const int tile = rest & 15;
    const int b    = rest >> 4;
    const int h0 = (tile >> 2) << 5;
    const int w0 = (tile & 3) << 5;
    const int tid = threadIdx.x;

    const int iLo = (d > 2) ? d - 2 : 0;
    const int iHi = (d < 7) ? d + 2 : 9;
    const int nI  = iHi - iLo + 1;

    // ---- load x tile (channels iLo..iHi) with halo ----
    const float* xb = x + b * (NC * HW * HW) + iLo * (HW * HW);
    for (int idx = tid; idx < nI * 1296; idx += 256) {
        int c   = idx / 1296;            // slot = i - iLo
        int rem = idx - c * 1296;
        int r   = rem / 36;
        int col = rem - r * 36;
        int gh = h0 + r - 2;
        int gw = w0 + col - 2;
        float v = 0.0f;
        if ((unsigned)gh < 128u && (unsigned)gw < 128u)
            v = __ldg(xb + c * (HW * HW) + gh * HW + gw);
        xs[(c * 36 + r) * 37 + col] = v;
    }
    // ---- this d's weight slice + bias ----
    {
        const float* wsrc = g_Wr + d * 1250;
        for (int idx = tid; idx < WS_FLOATS; idx += 256)
            ws[idx] = wsrc[idx];
    }
    if (tid < 10) bs[tid] = bias[tid];
    __syncthreads();

    const int hh = tid >> 3;
    const int ww = (tid & 7) << 2;
    float* outp = out + b * (100 * HW * HW) + d * (HW * HW)
                      + (h0 + hh) * HW + (w0 + ww);

    // bias pairs (o,o+1)
    u64 acc[5][4];
    {
        const u64* b2 = (const u64*)bs;
        #pragma unroll
        for (int o2 = 0; o2 < 5; ++o2) {
            u64 bv = b2[o2];
            #pragma unroll
            for (int p = 0; p < 4; ++p) acc[o2][p] = bv;
        }
    }

    for (int ii = 0; ii < nI; ++ii) {
        const int ip = (iLo + ii) - d + 2;
        const float* wbase = ws + ip * 250;            // 5kh x 5kw x 10o
        const float* xbase = xs + (ii * 36 + hh) * 37 + ww;

        #pragma unroll
        for (int kh = 0; kh < 5; ++kh) {
            const float* xr = xbase + kh * 37;
            float r[8];
            #pragma unroll
            for (int t = 0; t < 8; ++t) r[t] = xr[t];
            u64 rr[8];
            #pragma unroll
            for (int t = 0; t < 8; ++t) PACK2(rr[t], r[t], r[t]);

            const u64* wk2 = (const u64*)(wbase + kh * 50);   // 8B aligned
            #pragma unroll
            for (int kw = 0; kw < 5; ++kw) {
                u64 w[5];
                #pragma unroll
                for (int o2 = 0; o2 < 5; ++o2) w[o2] = wk2[kw * 5 + o2];
                #pragma unroll
                for (int o2 = 0; o2 < 5; ++o2) {
                    #pragma unroll
                    for (int p = 0; p < 4; ++p)
                        FMA2(acc[o2][p], w[o2], rr[kw + p], acc[o2][p]);
                }
            }
        }
    }

    // ---- store: two float4 per o-pair ----
    #pragma unroll
    for (int o2 = 0; o2 < 5; ++o2) {
        float lo0, hi0, lo1, hi1, lo2, hi2, lo3, hi3;
        UNPACK2(lo0, hi0, acc[o2][0]);
        UNPACK2(lo1, hi1, acc[o2][1]);
        UNPACK2(lo2, hi2, acc[o2][2]);
        UNPACK2(lo3, hi3, acc[o2][3]);
        float4 va = make_float4(lo0, lo1, lo2, lo3);
        float4 vb = make_float4(hi0, hi1, hi2, hi3);
        *(float4*)(outp + (2 * o2) * (10 * HW * HW))     = va;
        *(float4*)(outp + (2 * o2 + 1) * (10 * HW * HW)) = vb;
    }
}

extern "C" void kernel_launch(void* const* d_in, const int* in_sizes, int n_in,
                              void* d_out, int out_size) {
    const float* x    = (const float*)d_in[0];
    const float* W    = (const float*)d_in[1];
    const float* bias = (const float*)d_in[2];
    float* out = (float*)d_out;

    repack_kernel<<<49, 256>>>(W);

    const size_t smem_bytes = SMEM_FLOATS * sizeof(float);
    cudaFuncSetAttribute(conv_main, cudaFuncAttributeMaxDynamicSharedMemorySize,
                         (int)smem_bytes);

    conv_main<<<NB * 16 * 10, 256, smem_bytes>>>(x, bias, out);
}

// round 4
// speedup vs baseline: 1.0349x; 1.0349x over previous
#include <cuda_runtime.h>

// out[b,o,d,h,w] = bias[o] + sum_{i=d-2..d+2 in [0,10)} sum_{kh,kw}
//                    x[b,i,h+kh-2,w+kw-2] * W[o,i,i-d+2,kh,kw]
//
// Inputs: x[32,10,128,128] f32, W[10,10,5,5,5] f32, b[10] f32
// Output: [32,10,10,128,128] f32
//
// R4: R2's lean all-d-per-CTA inner loop + 3 CTAs/SM. Weights are staged
// per-d through a double-buffered 5KB smem slice (LDG prefetch overlapped
// with compute), cutting smem 102KB -> 64KB.

#define NB 32
#define NC 10
#define HW 128

typedef unsigned long long u64;

#define FMA2(d_, a_, b_, c_) \
    asm("fma.rn.f32x2 %0, %1, %2, %3;" : "=l"(d_) : "l"(a_), "l"(b_), "l"(c_))
#define PACK2(out_, lo_, hi_) \
    asm("mov.b64 %0, {%1, %2};" : "=l"(out_) : "f"(lo_), "f"(hi_))
#define UNPACK2(lo_, hi_, in_) \
    asm("mov.b64 {%0, %1}, %2;" : "=f"(lo_), "=f"(hi_) : "l"(in_))

// Repacked weights: [d][ip][kh][kw][o], zero where i=d+ip-2 out of range.
__device__ float g_Wr[10 * 5 * 5 * 5 * 10];

__global__ void repack_kernel(const float* __restrict__ W) {
    int idx = blockIdx.x * blockDim.x + threadIdx.x;
    if (idx >= 12500) return;
    int o    = idx % 10;
    int rest = idx / 10;
    int kw = rest % 5; rest /= 5;
    int kh = rest % 5; rest /= 5;
    int ip = rest % 5;
    int d  = rest / 5;
    int i = d + ip - 2;
    float v = 0.0f;
    if (i >= 0 && i < 10)
        v = W[o * 1250 + i * 125 + ip * 25 + kh * 5 + kw];
    g_Wr[idx] = v;
}

// SMEM: xs 10ch x 36 x pitch37 | ws double buffer 2x1250 | bs 10
#define XS_FLOATS (10 * 36 * 37)          // 13320
#define WSLICE 1250
#define SMEM_FLOATS (XS_FLOATS + 2 * WSLICE + 10)   // 15840 fl = 63360 B

__global__ __launch_bounds__(256, 3) void conv_main(
    const float* __restrict__ x,
    const float* __restrict__ bias,
    float* __restrict__ out)
{
    extern __shared__ float smem[];
    float* xs = smem;
    float* wsbuf = smem + XS_FLOATS;      // two slices of 1250, both 8B aligned
    float* bs = wsbuf + 2 * WSLICE;

    const int b    = blockIdx.x >> 4;
    const int tile = blockIdx.x & 15;
    const int h0 = (tile >> 2) << 5;
    const int w0 = (tile & 3) << 5;
    const int tid = threadIdx.x;

    // ---- load x tile with halo (all 10 channels) ----
    const float* xb = x + b * (NC * HW * HW);
    for (int idx = tid; idx < 10 * 36 * 36; idx += 256) {
        int c   = idx / 1296;
        int rem = idx - c * 1296;
        int r   = rem / 36;
        int col = rem - r * 36;
        int gh = h0 + r - 2;
        int gw = w0 + col - 2;
        float v = 0.0f;
        if ((unsigned)gh < 128u && (unsigned)gw < 128u)
            v = __ldg(xb + c * (HW * HW) + gh * HW + gw);
        xs[(c * 36 + r) * 37 + col] = v;
    }
    // ---- stage weight slice d=0 + bias ----
    {
        int i0 = tid, i1 = tid + 256, i2 = tid + 512, i3 = tid + 768, i4 = tid + 1024;
        wsbuf[i0] = g_Wr[i0];
        wsbuf[i1] = g_Wr[i1];
        wsbuf[i2] = g_Wr[i2];
        wsbuf[i3] = g_Wr[i3];
        if (i4 < WSLICE) wsbuf[i4] = g_Wr[i4];
    }
    if (tid < 10) bs[tid] = bias[tid];
    __syncthreads();

    const int hh = tid >> 3;
    const int ww = (tid & 7) << 2;
    float* outp = out + b * (100 * HW * HW) + (h0 + hh) * HW + (w0 + ww);

    // bias pairs packed once
    u64 bp[5];
    {
        const u64* b2 = (const u64*)bs;
        #pragma unroll
        for (int o2 = 0; o2 < 5; ++o2) bp[o2] = b2[o2];
    }

    for (int d = 0; d < 10; ++d) {
        const float* ws = wsbuf + (d & 1) * WSLICE;

        // prefetch next slice into registers (latency overlapped with compute)
        float wst[5];
        const bool pf = (d < 9);
        if (pf) {
            const float* src = g_Wr + (d + 1) * WSLICE;
            wst[0] = src[tid];
            wst[1] = src[tid + 256];
            wst[2] = src[tid + 512];
            wst[3] = src[tid + 768];
            wst[4] = (tid + 1024 < WSLICE) ? src[tid + 1024] : 0.0f;
        }

        u64 acc[5][4];
        #pragma unroll
        for (int o2 = 0; o2 < 5; ++o2)
            #pragma unroll
            for (int p = 0; p < 4; ++p) acc[o2][p] = bp[o2];

        const int iLo = (d > 2) ? d - 2 : 0;
        const int iHi = (d < 7) ? d + 2 : 9;

        for (int i = iLo; i <= iHi; ++i) {
            const int ip = i - d + 2;
            const float* wbase = ws + ip * 250;           // 5kh x 5kw x 10o
            const float* xbase = xs + (i * 36 + hh) * 37 + ww;

            #pragma unroll
            for (int kh = 0; kh < 5; ++kh) {
                const float* xr = xbase + kh * 37;
                float r[8];
                #pragma unroll
                for (int t = 0; t < 8; ++t) r[t] = xr[t];
                u64 rr[8];
                #pragma unroll
                for (int t = 0; t < 8; ++t) PACK2(rr[t], r[t], r[t]);

                const u64* wk2 = (const u64*)(wbase + kh * 50);   // 8B aligned
                #pragma unroll
                for (int kw = 0; kw < 5; ++kw) {
                    u64 w[5];
                    #pragma unroll
                    for (int o2 = 0; o2 < 5; ++o2) w[o2] = wk2[kw * 5 + o2];
                    #pragma unroll
                    for (int o2 = 0; o2 < 5; ++o2) {
                        #pragma unroll
                        for (int p = 0; p < 4; ++p)
                            FMA2(acc[o2][p], w[o2], rr[kw + p], acc[o2][p]);
                    }
                }
            }
        }

        // ---- store: two float4 per o-pair ----
        #pragma unroll
        for (int o2 = 0; o2 < 5; ++o2) {
            float lo0, hi0, lo1, hi1, lo2, hi2, lo3, hi3;
            UNPACK2(lo0, hi0, acc[o2][0]);
            UNPACK2(lo1, hi1, acc[o2][1]);
            UNPACK2(lo2, hi2, acc[o2][2]);
            UNPACK2(lo3, hi3, acc[o2][3]);
            float4 va = make_float4(lo0, lo1, lo2, lo3);
            float4 vb = make_float4(hi0, hi1, hi2, hi3);
            *(float4*)(outp + ((2 * o2) * 10 + d) * (HW * HW))     = va;
            *(float4*)(outp + ((2 * o2 + 1) * 10 + d) * (HW * HW)) = vb;
        }

        // commit prefetched slice, then publish to all warps
        if (pf) {
            float* dst = wsbuf + ((d + 1) & 1) * WSLICE;
            dst[tid]       = wst[0];
            dst[tid + 256] = wst[1];
            dst[tid + 512] = wst[2];
            dst[tid + 768] = wst[3];
            if (tid + 1024 < WSLICE) dst[tid + 1024] = wst[4];
        }
        __syncthreads();
    }
}

extern "C" void kernel_launch(void* const* d_in, const int* in_sizes, int n_in,
                              void* d_out, int out_size) {
    const float* x    = (const float*)d_in[0];
    const float* W    = (const float*)d_in[1];
    const float* bias = (const float*)d_in[2];
    float* out = (float*)d_out;

    repack_kernel<<<49, 256>>>(W);

    const size_t smem_bytes = SMEM_FLOATS * sizeof(float);
    cudaFuncSetAttribute(conv_main, cudaFuncAttributeMaxDynamicSharedMemorySize,
                         (int)smem_bytes);

    conv_main<<<NB * 16, 256, smem_bytes>>>(x, bias, out);
}

// round 5
// speedup vs baseline: 1.1399x; 1.1014x over previous
#include <cuda_runtime.h>

// out[b,o,d,h,w] = bias[o] + sum_{i=d-2..d+2 in [0,10)} sum_{kh,kw}
//                    x[b,i,h+kh-2,w+kw-2] * W[o,i,i-d+2,kh,kw]
//
// Inputs: x[32,10,128,128] f32, W[10,10,5,5,5] f32, b[10] f32
// Output: [32,10,10,128,128] f32
//
// R5: 128-thread CTAs on 16x32 tiles (grid 1024) -> 6 CTAs/SM, 24 warps,
// smooth wave schedule (R4's 512-CTA grid left a half-empty second wave).
// Inner FFMA2 loop identical to R4. Weights staged per-d via L1-hot LDG->STS.

#define NB 32
#define NC 10
#define HW 128

typedef unsigned long long u64;

#define FMA2(d_, a_, b_, c_) \
    asm("fma.rn.f32x2 %0, %1, %2, %3;" : "=l"(d_) : "l"(a_), "l"(b_), "l"(c_))
#define PACK2(out_, lo_, hi_) \
    asm("mov.b64 %0, {%1, %2};" : "=l"(out_) : "f"(lo_), "f"(hi_))
#define UNPACK2(lo_, hi_, in_) \
    asm("mov.b64 {%0, %1}, %2;" : "=f"(lo_), "=f"(hi_) : "l"(in_))

// Repacked weights: [d][ip][kh][kw][o], zero where i=d+ip-2 out of range.
__device__ float g_Wr[10 * 5 * 5 * 5 * 10];

__global__ void repack_kernel(const float* __restrict__ W) {
    int idx = blockIdx.x * blockDim.x + threadIdx.x;
    if (idx >= 12500) return;
    int o    = idx % 10;
    int rest = idx / 10;
    int kw = rest % 5; rest /= 5;
    int kh = rest % 5; rest /= 5;
    int ip = rest % 5;
    int d  = rest / 5;
    int i = d + ip - 2;
    float v = 0.0f;
    if (i >= 0 && i < 10)
        v = W[o * 1250 + i * 125 + ip * 25 + kh * 5 + kw];
    g_Wr[idx] = v;
}

// SMEM: xs 10ch x 20rows x pitch37 | ws 1250 | bs 10
#define XS_FLOATS (10 * 20 * 37)            // 7400
#define WSLICE 1250
#define SMEM_FLOATS (XS_FLOATS + WSLICE + 10)   // 8660 fl = 34640 B

__global__ __launch_bounds__(128, 6) void conv_main(
    const float* __restrict__ x,
    const float* __restrict__ bias,
    float* __restrict__ out)
{
    extern __shared__ float smem[];
    float* xs = smem;
    float* ws = smem + XS_FLOATS;      // byte off 29600, 8B aligned
    float* bs = ws + WSLICE;           // byte off 34600, 8B aligned

    const int b  = blockIdx.x >> 5;
    const int t  = blockIdx.x & 31;
    const int h0 = (t >> 2) << 4;      // 8 htiles of 16 rows
    const int w0 = (t & 3) << 5;       // 4 wtiles of 32 cols
    const int tid = threadIdx.x;

    // ---- load x tile with halo: 10 ch x 20 rows x 36 cols ----
    const float* xb = x + b * (NC * HW * HW);
    for (int idx = tid; idx < 10 * 20 * 36; idx += 128) {
        int c   = idx / 720;
        int rem = idx - c * 720;
        int r   = rem / 36;
        int col = rem - r * 36;
        int gh = h0 + r - 2;
        int gw = w0 + col - 2;
        float v = 0.0f;
        if ((unsigned)gh < 128u && (unsigned)gw < 128u)
            v = __ldg(xb + c * (HW * HW) + gh * HW + gw);
        xs[(c * 20 + r) * 37 + col] = v;
    }
    if (tid < 10) bs[tid] = bias[tid];
    // no sync here: first in-loop sync orders xs/bs writes before reads

    const int hh = tid >> 3;
    const int ww = (tid & 7) << 2;
    float* outp = out + b * (100 * HW * HW) + (h0 + hh) * HW + (w0 + ww);

    for (int d = 0; d < 10; ++d) {
        // ---- stage this d's weight slice (L1-hot: shared by all CTAs) ----
        {
            const float* src = g_Wr + d * WSLICE;
            for (int idx = tid; idx < WSLICE; idx += 128)
                ws[idx] = __ldg(src + idx);
        }
        __syncthreads();

        u64 acc[5][4];
        {
            const u64* b2 = (const u64*)bs;
            #pragma unroll
            for (int o2 = 0; o2 < 5; ++o2) {
                u64 bv = b2[o2];
                #pragma unroll
                for (int p = 0; p < 4; ++p) acc[o2][p] = bv;
            }
        }

        const int iLo = (d > 2) ? d - 2 : 0;
        const int iHi = (d < 7) ? d + 2 : 9;

        for (int i = iLo; i <= iHi; ++i) {
            const int ip = i - d + 2;
            const float* wbase = ws + ip * 250;           // 5kh x 5kw x 10o
            const float* xbase = xs + (i * 20 + hh) * 37 + ww;

            #pragma unroll
            for (int kh = 0; kh < 5; ++kh) {
                const float* xr = xbase + kh * 37;
                float r[8];
                #pragma unroll
                for (int tt = 0; tt < 8; ++tt) r[tt] = xr[tt];
                u64 rr[8];
                #pragma unroll
                for (int tt = 0; tt < 8; ++tt) PACK2(rr[tt], r[tt], r[tt]);

                const u64* wk2 = (const u64*)(wbase + kh * 50);   // 8B aligned
                #pragma unroll
                for (int kw = 0; kw < 5; ++kw) {
                    u64 w[5];
                    #pragma unroll
                    for (int o2 = 0; o2 < 5; ++o2) w[o2] = wk2[kw * 5 + o2];
                    #pragma unroll
                    for (int o2 = 0; o2 < 5; ++o2) {
                        #pragma unroll
                        for (int p = 0; p < 4; ++p)
                            FMA2(acc[o2][p], w[o2], rr[kw + p], acc[o2][p]);
                    }
                }
            }
        }

        // ---- store: two float4 per o-pair ----
        #pragma unroll
        for (int o2 = 0; o2 < 5; ++o2) {
            float lo0, hi0, lo1, hi1, lo2, hi2, lo3, hi3;
            UNPACK2(lo0, hi0, acc[o2][0]);
            UNPACK2(lo1, hi1, acc[o2][1]);
            UNPACK2(lo2, hi2, acc[o2][2]);
            UNPACK2(lo3, hi3, acc[o2][3]);
            float4 va = make_float4(lo0, lo1, lo2, lo3);
            float4 vb = make_float4(hi0, hi1, hi2, hi3);
            *(float4*)(outp + ((2 * o2) * 10 + d) * (HW * HW))     = va;
            *(float4*)(outp + ((2 * o2 + 1) * 10 + d) * (HW * HW)) = vb;
        }

        __syncthreads();   // compute(d) done before ws overwrite at d+1
    }
}

extern "C" void kernel_launch(void* const* d_in, const int* in_sizes, int n_in,
                              void* d_out, int out_size) {
    const float* x    = (const float*)d_in[0];
    const float* W    = (const float*)d_in[1];
    const float* bias = (const float*)d_in[2];
    float* out = (float*)d_out;

    repack_kernel<<<49, 256>>>(W);

    const size_t smem_bytes = SMEM_FLOATS * sizeof(float);
    cudaFuncSetAttribute(conv_main, cudaFuncAttributeMaxDynamicSharedMemorySize,
                         (int)smem_bytes);

    conv_main<<<NB * 32, 128, smem_bytes>>>(x, bias, out);
}